// round 16
// baseline (speedup 1.0000x reference)
#include <cuda_runtime.h>
#include <math.h>

#define NN 12000
#define EE 400000

// ---------------- scratch (static device globals; no allocation) ----------------
// cnt arrays are zero at process start (static zero-init) and re-zeroed by
// k_scan after consumption, so every kernel_launch invocation sees zeros.
__device__ int   d_cnt_src[NN];
__device__ int   d_cnt_dst[NN];
__device__ int   d_rp_src[NN + 1];
__device__ int   d_rp_dst[NN + 1];
__device__ int   d_slot_src[EE];   // per-edge rank within src bucket (-1 = skip)
__device__ int   d_slot_dst[EE];   // per-edge rank within dst bucket (-1 = skip)
__device__ int   d_nb_src[EE];     // neighbors (dst) grouped by src, self-edges excluded
__device__ int   d_nb_dst[EE];     // neighbors (src) grouped by dst, all edges
__device__ float d_dis[NN];        // dense-path  deg^-1/2
__device__ float d_dinv[NN];       // sparse-path deg^-1/2
__device__ __align__(16) float d_bufA[NN * 128];
__device__ __align__(16) float d_bufB[NN * 128];
__device__ __align__(16) float d_split[NN * 256];  // L1 split-K partial planes (8 x 32)
__device__ __align__(16) float d_g[NN * 8];   // L5 pre-agg logits, padded stride 8

static inline int cdiv(int a, int b) { return (a + b - 1) / b; }

template<int SEL>
__device__ __forceinline__ float* buf_ptr() {
    if (SEL == 1) return d_bufA;
    if (SEL == 3) return d_split;
    return d_bufB;
}

// ---------------- per-block edge dtype detection ----------------
__device__ __forceinline__ int block_detect_is64(const int* __restrict__ e32) {
    int nz = 0;
    for (int k = threadIdx.x; k < 1024; k += blockDim.x)
        nz |= (e32[2 * k + 1] != 0);
    return __syncthreads_or(nz) ? 0 : 1;
}

// ---------------- CSR build pass 1: count + record per-edge slot ----------------
__global__ void k_count(const int* __restrict__ e32) {
    int is64 = block_detect_is64(e32);
    int e = blockIdx.x * blockDim.x + threadIdx.x;
    if (e >= EE) return;
    int s, d;
    if (is64) { s = e32[2 * e]; d = e32[2 * (EE + e)]; }
    else      { s = e32[e];     d = e32[EE + e]; }
    int p = ((unsigned)d < NN) ? atomicAdd(&d_cnt_dst[d], 1) : -1;
    int q = ((unsigned)s < NN && s != d) ? atomicAdd(&d_cnt_src[s], 1) : -1;
    d_slot_dst[e] = p;
    d_slot_src[e] = q;
}

// single-block scan, 1024 threads, 12 contiguous elements per thread.
__global__ void k_scan() {
    __shared__ int wsum[32];
    constexpr int CH = 12;  // 1024 * 12 = 12288 >= NN
    int t = threadIdx.x;
    int lane = t & 31, wid = t >> 5;
    for (int which = 0; which < 2; which++) {
        int* cnt = which ? d_cnt_dst : d_cnt_src;
        int* rp  = which ? d_rp_dst  : d_rp_src;
        float* nrm = which ? d_dinv : d_dis;

        int base = t * CH;
        int v[CH];
        int s = 0;
#pragma unroll
        for (int k = 0; k < CH; k++) {
            int i = base + k;
            int x = (i < NN) ? cnt[i] : 0;
            if (i < NN) cnt[i] = 0;    // re-zero for next invocation
            v[k] = x; s += x;
        }
        int sc = s;
#pragma unroll
        for (int off = 1; off < 32; off <<= 1) {
            int y = __shfl_up_sync(0xFFFFFFFFu, sc, off);
            if (lane >= off) sc += y;
        }
        if (lane == 31) wsum[wid] = sc;
        __syncthreads();
        if (wid == 0) {
            int ws = wsum[lane];
#pragma unroll
            for (int off = 1; off < 32; off <<= 1) {
                int y = __shfl_up_sync(0xFFFFFFFFu, ws, off);
                if (lane >= off) ws += y;
            }
            wsum[lane] = ws;
        }
        __syncthreads();
        int run = sc - s + (wid > 0 ? wsum[wid - 1] : 0);
#pragma unroll
        for (int k = 0; k < CH; k++) {
            int i = base + k;
            if (i < NN) {
                nrm[i] = rsqrtf((float)(v[k] + 1));  // +1: diag=1 (dense) / self loop (sparse)
                run += v[k];
                rp[i + 1] = run;
            }
        }
        if (t == 0) rp[0] = 0;
        __syncthreads();
    }
}

// ---------------- CSR build pass 2: place edges (NO atomics) ----------------
__global__ void k_place(const int* __restrict__ e32) {
    int is64 = block_detect_is64(e32);
    int e = blockIdx.x * blockDim.x + threadIdx.x;
    if (e >= EE) return;
    int s, d;
    if (is64) { s = e32[2 * e]; d = e32[2 * (EE + e)]; }
    else      { s = e32[e];     d = e32[EE + e]; }
    int pd = d_slot_dst[e];
    int ps = d_slot_src[e];
    if (pd >= 0) d_nb_dst[d_rp_dst[d] + pd] = s;
    if (ps >= 0) d_nb_src[d_rp_src[s] + ps] = d;
}

// ---------------- GEMM: Y = X[N,DIN] @ W[DIN,DOUT] (+bias, +relu) ----------------
// IN_SEL: 0 = external pointer arg, 1 = d_bufA, 2 = d_bufB, 3 = d_split.  OUT same.
// KSPLIT: blockIdx.y handles K-range [by*DIN/KSPLIT, (by+1)*DIN/KSPLIT); output
// plane by written at column offset by*DOUT with row stride DOUT*KSPLIT.
template<int DIN, int DOUT, int BM, int BK, int TM, int KSPLIT,
         bool RELU, bool BIAS, int IN_SEL, int OUT_SEL>
__global__ void k_gemm(const float* __restrict__ Xext, const float* __restrict__ W,
                       const float* __restrict__ bias) {
    const float* X = (IN_SEL == 0) ? Xext : (const float*)buf_ptr<IN_SEL>();
    float* Y = buf_ptr<OUT_SEL>();

    constexpr int TN = 4;
    constexpr int TX = DOUT / TN, TY = BM / TM;
    constexpr int NT = TX * TY;
    constexpr int KLEN = DIN / KSPLIT;
    static_assert(BK % 4 == 0 && KLEN % BK == 0, "");
    __shared__ float Xs[BM][BK + 1];
    __shared__ __align__(16) float Ws[BK][DOUT];

    int tx = threadIdx.x, ty = threadIdx.y;
    int tid = ty * TX + tx;
    int row0 = blockIdx.x * BM;
    int kbase = blockIdx.y * KLEN;

    float acc[TM][TN];
#pragma unroll
    for (int i = 0; i < TM; i++)
#pragma unroll
        for (int j = 0; j < TN; j++) acc[i][j] = 0.f;

    for (int k0 = kbase; k0 < kbase + KLEN; k0 += BK) {
        constexpr int XF4 = BM * BK / 4;
#pragma unroll
        for (int idx = tid; idx < XF4; idx += NT) {
            int r = idx / (BK / 4), c4 = idx % (BK / 4);
            int gr = row0 + r;
            float4 xv = make_float4(0.f, 0.f, 0.f, 0.f);
            if (gr < NN) xv = *reinterpret_cast<const float4*>(&X[gr * DIN + k0 + c4 * 4]);
            Xs[r][c4 * 4 + 0] = xv.x;
            Xs[r][c4 * 4 + 1] = xv.y;
            Xs[r][c4 * 4 + 2] = xv.z;
            Xs[r][c4 * 4 + 3] = xv.w;
        }
        constexpr int WF4 = BK * DOUT / 4;
#pragma unroll
        for (int idx = tid; idx < WF4; idx += NT) {
            int r = idx / (DOUT / 4), c4 = idx % (DOUT / 4);
            *reinterpret_cast<float4*>(&Ws[r][c4 * 4]) =
                *reinterpret_cast<const float4*>(&W[(k0 + r) * DOUT + c4 * 4]);
        }
        __syncthreads();
#pragma unroll
        for (int kk = 0; kk < BK; kk++) {
            float a[TM];
#pragma unroll
            for (int i = 0; i < TM; i++) a[i] = Xs[ty * TM + i][kk];
            float4 wv = *reinterpret_cast<const float4*>(&Ws[kk][tx * TN]);
            float w[TN] = {wv.x, wv.y, wv.z, wv.w};
#pragma unroll
            for (int i = 0; i < TM; i++)
#pragma unroll
                for (int j = 0; j < TN; j++) acc[i][j] += a[i] * w[j];
        }
        __syncthreads();
    }
    int cbase = blockIdx.y * DOUT;
#pragma unroll
    for (int i = 0; i < TM; i++) {
        int gr = row0 + ty * TM + i;
        if (gr < NN) {
#pragma unroll
            for (int j = 0; j < TN; j++) {
                int c = tx * TN + j;
                float r = acc[i][j];
                if (BIAS) r += bias[c];
                if (RELU) r = fmaxf(r, 0.f);
                Y[gr * (DOUT * KSPLIT) + cbase + c] = r;
            }
        }
    }
}

// ---------------- reduce 8 K-split planes: d_split[NN][8x32] -> bufB[NN][32] ----------------
__global__ void k_reduce8() {
    int i = blockIdx.x * blockDim.x + threadIdx.x;   // i in [0, NN*8): 8 float4 groups/row
    if (i >= NN * 8) return;
    int row = i >> 3, c4 = i & 7;
    const float4* A = (const float4*)d_split;
    // row stride in float4 units: 256/4 = 64; plane offset: 32 floats = 8 float4
    float4 r = A[row * 64 + c4];
#pragma unroll
    for (int pl = 1; pl < 8; pl++) {
        float4 v = A[row * 64 + pl * 8 + c4];
        r.x += v.x; r.y += v.y; r.z += v.z; r.w += v.w;
    }
    ((float4*)d_bufB)[row * 8 + c4] = r;
}

// ---------------- aggregation: warp per node, lane per V channels, unroll 8 ----------------
template<int D, bool BIASRELU, int IN_SEL, bool DENSE>
__global__ void k_agg(const float* __restrict__ bias) {
    const float* X = buf_ptr<IN_SEL>();
    float* Y = buf_ptr<IN_SEL == 1 ? 2 : 1>();
    const int*   rp  = DENSE ? d_rp_src : d_rp_dst;
    const int*   nb  = DENSE ? d_nb_src : d_nb_dst;
    const float* nrm = DENSE ? d_dis    : d_dinv;

    constexpr int V = D / 32;  // 1, 2 or 4
    int gw = (blockIdx.x * blockDim.x + threadIdx.x) >> 5;
    int lane = threadIdx.x & 31;
    if (gw >= NN) return;

    float acc[V];
#pragma unroll
    for (int v = 0; v < V; v++) acc[v] = 0.f;

    int beg = rp[gw], end = rp[gw + 1];
    int p = beg;
    constexpr int U = 8;
    for (; p + U <= end; p += U) {
        int j[U]; float n[U];
#pragma unroll
        for (int u = 0; u < U; u++) j[u] = nb[p + u];
#pragma unroll
        for (int u = 0; u < U; u++) n[u] = nrm[j[u]];
        if (V == 4) {
            float4 x[U];
#pragma unroll
            for (int u = 0; u < U; u++) x[u] = *(const float4*)&X[j[u] * D + lane * 4];
#pragma unroll
            for (int u = 0; u < U; u++) {
                acc[0] += n[u] * x[u].x; acc[1] += n[u] * x[u].y;
                acc[2] += n[u] * x[u].z; acc[3] += n[u] * x[u].w;
            }
        } else if (V == 2) {
            float2 x[U];
#pragma unroll
            for (int u = 0; u < U; u++) x[u] = *(const float2*)&X[j[u] * D + lane * 2];
#pragma unroll
            for (int u = 0; u < U; u++) { acc[0] += n[u] * x[u].x; acc[1] += n[u] * x[u].y; }
        } else {
            float x[U];
#pragma unroll
            for (int u = 0; u < U; u++) x[u] = X[j[u] * D + lane];
#pragma unroll
            for (int u = 0; u < U; u++) acc[0] += n[u] * x[u];
        }
    }
    for (; p < end; p++) {
        int j = nb[p];
        float nj = nrm[j];
        if (V == 4) {
            float4 x = *(const float4*)&X[j * D + lane * 4];
            acc[0] += nj * x.x; acc[1] += nj * x.y; acc[2] += nj * x.z; acc[3] += nj * x.w;
        } else if (V == 2) {
            float2 x = *(const float2*)&X[j * D + lane * 2];
            acc[0] += nj * x.x; acc[1] += nj * x.y;
        } else {
            acc[0] += nj * X[j * D + lane];
        }
    }
    float ni = nrm[gw], ni2 = ni * ni;
#pragma unroll
    for (int v = 0; v < V; v++) {
        float r = ni * acc[v] + ni2 * X[gw * D + lane * V + v];
        if (BIASRELU) r = fmaxf(r + bias[lane * V + v], 0.f);
        Y[gw * D + lane * V + v] = r;
    }
}

// ---------------- L5 GEMM: warp per row, bufA[N,128] @ W[128,6] -> d_g ----------------
__global__ void k_gemm6(const float* __restrict__ W) {
    const float* X = d_bufA;
    int row = (blockIdx.x * blockDim.x + threadIdx.x) >> 5;
    int lane = threadIdx.x & 31;
    if (row >= NN) return;
    float acc[6] = {0.f, 0.f, 0.f, 0.f, 0.f, 0.f};
#pragma unroll
    for (int kb = 0; kb < 4; kb++) {
        int k = kb * 32 + lane;
        float x = X[row * 128 + k];
#pragma unroll
        for (int c = 0; c < 6; c++) acc[c] += x * W[k * 6 + c];
    }
#pragma unroll
    for (int c = 0; c < 6; c++) {
#pragma unroll
        for (int off = 16; off >= 1; off >>= 1)
            acc[c] += __shfl_xor_sync(0xFFFFFFFF, acc[c], off);
    }
    if (lane == 0) {
#pragma unroll
        for (int c = 0; c < 6; c++) d_g[row * 8 + c] = acc[c];
    }
}

// ---------------- final: sparse agg over 6 channels + bias + log_softmax ----------------
__global__ void k_final(const float* __restrict__ b2, float* __restrict__ out) {
    int i = blockIdx.x * blockDim.x + threadIdx.x;
    if (i >= NN) return;
    float a0 = 0, a1 = 0, a2 = 0, a3 = 0, a4 = 0, a5 = 0;
    int beg = d_rp_dst[i], end = d_rp_dst[i + 1];
    int p = beg;
    for (; p + 2 <= end; p += 2) {
        int j0 = d_nb_dst[p], j1 = d_nb_dst[p + 1];
        float n0 = d_dinv[j0], n1 = d_dinv[j1];
        float4 u0 = *(const float4*)&d_g[j0 * 8];
        float2 v0 = *(const float2*)&d_g[j0 * 8 + 4];
        float4 u1 = *(const float4*)&d_g[j1 * 8];
        float2 v1 = *(const float2*)&d_g[j1 * 8 + 4];
        a0 += n0 * u0.x + n1 * u1.x;  a1 += n0 * u0.y + n1 * u1.y;
        a2 += n0 * u0.z + n1 * u1.z;  a3 += n0 * u0.w + n1 * u1.w;
        a4 += n0 * v0.x + n1 * v1.x;  a5 += n0 * v0.y + n1 * v1.y;
    }
    for (; p < end; p++) {
        int j = d_nb_dst[p];
        float nj = d_dinv[j];
        float4 u = *(const float4*)&d_g[j * 8];
        float2 v = *(const float2*)&d_g[j * 8 + 4];
        a0 += nj * u.x; a1 += nj * u.y; a2 += nj * u.z;
        a3 += nj * u.w; a4 += nj * v.x; a5 += nj * v.y;
    }
    float ni = d_dinv[i], ni2 = ni * ni;
    float4 su = *(const float4*)&d_g[i * 8];
    float2 sv = *(const float2*)&d_g[i * 8 + 4];
    float r[6];
    r[0] = ni * a0 + ni2 * su.x + b2[0];
    r[1] = ni * a1 + ni2 * su.y + b2[1];
    r[2] = ni * a2 + ni2 * su.z + b2[2];
    r[3] = ni * a3 + ni2 * su.w + b2[3];
    r[4] = ni * a4 + ni2 * sv.x + b2[4];
    r[5] = ni * a5 + ni2 * sv.y + b2[5];
    float m = r[0];
#pragma unroll
    for (int c = 1; c < 6; c++) m = fmaxf(m, r[c]);
    float s = 0.f;
#pragma unroll
    for (int c = 0; c < 6; c++) s += expf(r[c] - m);
    float l = logf(s);
#pragma unroll
    for (int c = 0; c < 6; c++) out[i * 6 + c] = r[c] - m - l;
}

// ---------------- launch ----------------
static int idx_of(const int* in_sizes, int n_in, int size, int ordinal) {
    int c = 0;
    for (int i = 0; i < n_in; i++) {
        if (in_sizes[i] == size) {
            if (c == ordinal) return i;
            c++;
        }
    }
    return 0;
}

extern "C" void kernel_launch(void* const* d_in, const int* in_sizes, int n_in,
                              void* d_out, int out_size) {
    const float* feats = (const float*)d_in[idx_of(in_sizes, n_in, NN * 512, 0)];
    const int*   e32   = (const int*)d_in[idx_of(in_sizes, n_in, 2 * EE, 0)];
    const float* W1  = (const float*)d_in[idx_of(in_sizes, n_in, 512 * 32, 0)];
    const float* b1  = (const float*)d_in[idx_of(in_sizes, n_in, 32, 0)];
    const float* W12 = (const float*)d_in[idx_of(in_sizes, n_in, 32 * 64, 0)];
    const float* b12 = (const float*)d_in[idx_of(in_sizes, n_in, 64, 0)];
    const float* W13 = (const float*)d_in[idx_of(in_sizes, n_in, 64 * 128, 0)];
    const float* b13 = (const float*)d_in[idx_of(in_sizes, n_in, 128, 0)];
    const float* W14 = (const float*)d_in[idx_of(in_sizes, n_in, 128 * 128, 1)];  // 2nd 16384
    const float* b14 = (const float*)d_in[idx_of(in_sizes, n_in, 128, 1)];        // 2nd 128
    const float* W2  = (const float*)d_in[idx_of(in_sizes, n_in, 128 * 6, 0)];
    const float* b2  = (const float*)d_in[idx_of(in_sizes, n_in, 6, 0)];
    float* out = (float*)d_out;

    // graph structure (cnt arrays are zero: static init + re-zero in k_scan)
    k_count<<<cdiv(EE, 256), 256>>>(e32);
    k_scan<<<1, 1024>>>();
    k_place<<<cdiv(EE, 256), 256>>>(e32);

    // L1: split-K(8) GEMM feats@W1: grid (94,8) = 752 blocks. Partial planes in
    // d_split[NN][8x32]; reduce to bufB[NN][32].
    k_gemm<512, 32, 128, 32, 4, 8, false, false, 0, 3>
        <<<dim3(cdiv(NN, 128), 8), dim3(8, 32)>>>(feats, W1, nullptr);
    k_reduce8<<<cdiv(NN * 8, 256), 256>>>();
    // dense agg (B->A) + b1 + relu
    k_agg<32, true, 2, true><<<cdiv(NN * 32, 256), 256>>>(b1);

    // L2: dense agg at 32 (A->B), then GEMM 32->64 (B->A) + b12 + relu
    k_agg<32, false, 1, true><<<cdiv(NN * 32, 256), 256>>>(nullptr);
    k_gemm<32, 64, 64, 16, 4, 1, true, true, 2, 1><<<cdiv(NN, 64), dim3(16, 16)>>>(nullptr, W12, b12);

    // L3: sparse agg at 64 (A->B), then GEMM 64->128 (B->A) + b13 + relu
    k_agg<64, false, 1, false><<<cdiv(NN * 32, 256), 256>>>(nullptr);
    k_gemm<64, 128, 64, 16, 8, 1, true, true, 2, 1><<<cdiv(NN, 64), dim3(32, 8)>>>(nullptr, W13, b13);

    // L4: sparse agg at 128 (A->B), then GEMM 128->128 (B->A) + b14 + relu
    k_agg<128, false, 1, false><<<cdiv(NN * 32, 256), 256>>>(nullptr);
    k_gemm<128, 128, 64, 16, 8, 1, true, true, 2, 1><<<cdiv(NN, 64), dim3(32, 8)>>>(nullptr, W14, b14);

    // L5: GEMM 128->6 first (A -> d_g), then sparse agg at 6 + b2 + log_softmax
    k_gemm6<<<cdiv(NN * 32, 256), 256>>>(W2);
    k_final<<<cdiv(NN, 256), 256>>>(b2, out);
}

// round 17
// speedup vs baseline: 1.0306x; 1.0306x over previous
#include <cuda_runtime.h>
#include <math.h>

#define NN 12000
#define EE 400000

// ---------------- scratch (static device globals; no allocation) ----------------
// cnt arrays are zero at process start (static zero-init) and re-zeroed by
// k_scan after consumption, so every kernel_launch invocation sees zeros.
__device__ int   d_is64g;          // edge dtype verdict, published by k_count block 0
__device__ int   d_cnt_src[NN];
__device__ int   d_cnt_dst[NN];
__device__ int   d_rp_src[NN + 1];
__device__ int   d_rp_dst[NN + 1];
__device__ int   d_slot_src[EE];   // per-edge rank within src bucket (-1 = skip)
__device__ int   d_slot_dst[EE];   // per-edge rank within dst bucket (-1 = skip)
__device__ int   d_nb_src[EE];     // neighbors (dst) grouped by src, self-edges excluded
__device__ int   d_nb_dst[EE];     // neighbors (src) grouped by dst, all edges
__device__ float d_dis[NN];        // dense-path  deg^-1/2
__device__ float d_dinv[NN];       // sparse-path deg^-1/2
__device__ __align__(16) float d_bufA[NN * 128];
__device__ __align__(16) float d_bufB[NN * 128];
__device__ __align__(16) float d_split[NN * 256];  // L1 split-K partial planes (8 x 32)
__device__ __align__(16) float d_g[NN * 8];   // L5 pre-agg logits, padded stride 8

static inline int cdiv(int a, int b) { return (a + b - 1) / b; }

template<int SEL>
__device__ __forceinline__ float* buf_ptr() {
    if (SEL == 1) return d_bufA;
    if (SEL == 3) return d_split;
    return d_bufB;
}

// ---------------- per-block edge dtype detection ----------------
// View edges as int32 words. If really int64 (values < 2^31), every odd word is
// a zero high-word; int32 node-id data cannot have 1024 consecutive zero odd
// words. Deterministic, identical verdict in every block.
__device__ __forceinline__ int block_detect_is64(const int* __restrict__ e32) {
    int nz = 0;
    for (int k = threadIdx.x; k < 1024; k += blockDim.x)
        nz |= (e32[2 * k + 1] != 0);
    return __syncthreads_or(nz) ? 0 : 1;
}

// ---------------- CSR build pass 1: count + record per-edge slot ----------------
__global__ void k_count(const int* __restrict__ e32) {
    int is64 = block_detect_is64(e32);
    if (blockIdx.x == 0 && threadIdx.x == 0) d_is64g = is64;  // publish for k_place
    int e = blockIdx.x * blockDim.x + threadIdx.x;
    if (e >= EE) return;
    int s, d;
    if (is64) { s = e32[2 * e]; d = e32[2 * (EE + e)]; }
    else      { s = e32[e];     d = e32[EE + e]; }
    int p = ((unsigned)d < NN) ? atomicAdd(&d_cnt_dst[d], 1) : -1;
    int q = ((unsigned)s < NN && s != d) ? atomicAdd(&d_cnt_src[s], 1) : -1;
    d_slot_dst[e] = p;
    d_slot_src[e] = q;
}

// single-block scan, 1024 threads, 12 contiguous elements per thread.
__global__ void k_scan() {
    __shared__ int wsum[32];
    constexpr int CH = 12;  // 1024 * 12 = 12288 >= NN
    int t = threadIdx.x;
    int lane = t & 31, wid = t >> 5;
    for (int which = 0; which < 2; which++) {
        int* cnt = which ? d_cnt_dst : d_cnt_src;
        int* rp  = which ? d_rp_dst  : d_rp_src;
        float* nrm = which ? d_dinv : d_dis;

        int base = t * CH;
        int v[CH];
        int s = 0;
#pragma unroll
        for (int k = 0; k < CH; k++) {
            int i = base + k;
            int x = (i < NN) ? cnt[i] : 0;
            if (i < NN) cnt[i] = 0;    // re-zero for next invocation
            v[k] = x; s += x;
        }
        int sc = s;
#pragma unroll
        for (int off = 1; off < 32; off <<= 1) {
            int y = __shfl_up_sync(0xFFFFFFFFu, sc, off);
            if (lane >= off) sc += y;
        }
        if (lane == 31) wsum[wid] = sc;
        __syncthreads();
        if (wid == 0) {
            int ws = wsum[lane];
#pragma unroll
            for (int off = 1; off < 32; off <<= 1) {
                int y = __shfl_up_sync(0xFFFFFFFFu, ws, off);
                if (lane >= off) ws += y;
            }
            wsum[lane] = ws;
        }
        __syncthreads();
        int run = sc - s + (wid > 0 ? wsum[wid - 1] : 0);
#pragma unroll
        for (int k = 0; k < CH; k++) {
            int i = base + k;
            if (i < NN) {
                nrm[i] = rsqrtf((float)(v[k] + 1));  // +1: diag=1 (dense) / self loop (sparse)
                run += v[k];
                rp[i + 1] = run;
            }
        }
        if (t == 0) rp[0] = 0;
        __syncthreads();
    }
}

// ---------------- CSR build pass 2: place edges (NO atomics) ----------------
__global__ void k_place(const int* __restrict__ e32) {
    int is64 = d_is64g;   // published by k_count (same invocation, earlier kernel)
    int e = blockIdx.x * blockDim.x + threadIdx.x;
    if (e >= EE) return;
    int s, d;
    if (is64) { s = e32[2 * e]; d = e32[2 * (EE + e)]; }
    else      { s = e32[e];     d = e32[EE + e]; }
    int pd = d_slot_dst[e];
    int ps = d_slot_src[e];
    if (pd >= 0) d_nb_dst[d_rp_dst[d] + pd] = s;
    if (ps >= 0) d_nb_src[d_rp_src[s] + ps] = d;
}

// ---------------- GEMM: Y = X[N,DIN] @ W[DIN,DOUT] (+bias, +relu) ----------------
// IN_SEL: 0 = external pointer arg, 1 = d_bufA, 2 = d_bufB, 3 = d_split.  OUT same.
// KSPLIT: blockIdx.y handles K-range [by*DIN/KSPLIT, (by+1)*DIN/KSPLIT); output
// plane by written at column offset by*DOUT with row stride DOUT*KSPLIT.
template<int DIN, int DOUT, int BM, int BK, int TM, int KSPLIT,
         bool RELU, bool BIAS, int IN_SEL, int OUT_SEL>
__global__ void k_gemm(const float* __restrict__ Xext, const float* __restrict__ W,
                       const float* __restrict__ bias) {
    const float* X = (IN_SEL == 0) ? Xext : (const float*)buf_ptr<IN_SEL>();
    float* Y = buf_ptr<OUT_SEL>();

    constexpr int TN = 4;
    constexpr int TX = DOUT / TN, TY = BM / TM;
    constexpr int NT = TX * TY;
    constexpr int KLEN = DIN / KSPLIT;
    static_assert(BK % 4 == 0 && KLEN % BK == 0, "");
    __shared__ float Xs[BM][BK + 1];
    __shared__ __align__(16) float Ws[BK][DOUT];

    int tx = threadIdx.x, ty = threadIdx.y;
    int tid = ty * TX + tx;
    int row0 = blockIdx.x * BM;
    int kbase = blockIdx.y * KLEN;

    float acc[TM][TN];
#pragma unroll
    for (int i = 0; i < TM; i++)
#pragma unroll
        for (int j = 0; j < TN; j++) acc[i][j] = 0.f;

    for (int k0 = kbase; k0 < kbase + KLEN; k0 += BK) {
        constexpr int XF4 = BM * BK / 4;
#pragma unroll
        for (int idx = tid; idx < XF4; idx += NT) {
            int r = idx / (BK / 4), c4 = idx % (BK / 4);
            int gr = row0 + r;
            float4 xv = make_float4(0.f, 0.f, 0.f, 0.f);
            if (gr < NN) xv = *reinterpret_cast<const float4*>(&X[gr * DIN + k0 + c4 * 4]);
            Xs[r][c4 * 4 + 0] = xv.x;
            Xs[r][c4 * 4 + 1] = xv.y;
            Xs[r][c4 * 4 + 2] = xv.z;
            Xs[r][c4 * 4 + 3] = xv.w;
        }
        constexpr int WF4 = BK * DOUT / 4;
#pragma unroll
        for (int idx = tid; idx < WF4; idx += NT) {
            int r = idx / (DOUT / 4), c4 = idx % (DOUT / 4);
            *reinterpret_cast<float4*>(&Ws[r][c4 * 4]) =
                *reinterpret_cast<const float4*>(&W[(k0 + r) * DOUT + c4 * 4]);
        }
        __syncthreads();
#pragma unroll
        for (int kk = 0; kk < BK; kk++) {
            float a[TM];
#pragma unroll
            for (int i = 0; i < TM; i++) a[i] = Xs[ty * TM + i][kk];
            float4 wv = *reinterpret_cast<const float4*>(&Ws[kk][tx * TN]);
            float w[TN] = {wv.x, wv.y, wv.z, wv.w};
#pragma unroll
            for (int i = 0; i < TM; i++)
#pragma unroll
                for (int j = 0; j < TN; j++) acc[i][j] += a[i] * w[j];
        }
        __syncthreads();
    }
    int cbase = blockIdx.y * DOUT;
#pragma unroll
    for (int i = 0; i < TM; i++) {
        int gr = row0 + ty * TM + i;
        if (gr < NN) {
#pragma unroll
            for (int j = 0; j < TN; j++) {
                int c = tx * TN + j;
                float r = acc[i][j];
                if (BIAS) r += bias[c];
                if (RELU) r = fmaxf(r, 0.f);
                Y[gr * (DOUT * KSPLIT) + cbase + c] = r;
            }
        }
    }
}

// ---------------- reduce 8 K-split planes: d_split[NN][8x32] -> bufB[NN][32] ----------------
__global__ void k_reduce8() {
    int i = blockIdx.x * blockDim.x + threadIdx.x;   // i in [0, NN*8): 8 float4 groups/row
    if (i >= NN * 8) return;
    int row = i >> 3, c4 = i & 7;
    const float4* A = (const float4*)d_split;
    // row stride in float4 units: 256/4 = 64; plane offset: 32 floats = 8 float4
    float4 r = A[row * 64 + c4];
#pragma unroll
    for (int pl = 1; pl < 8; pl++) {
        float4 v = A[row * 64 + pl * 8 + c4];
        r.x += v.x; r.y += v.y; r.z += v.z; r.w += v.w;
    }
    ((float4*)d_bufB)[row * 8 + c4] = r;
}

// ---------------- aggregation: warp per node, lane per V channels, unroll 8 ----------------
template<int D, bool BIASRELU, int IN_SEL, bool DENSE>
__global__ void k_agg(const float* __restrict__ bias) {
    const float* X = buf_ptr<IN_SEL>();
    float* Y = buf_ptr<IN_SEL == 1 ? 2 : 1>();
    const int*   rp  = DENSE ? d_rp_src : d_rp_dst;
    const int*   nb  = DENSE ? d_nb_src : d_nb_dst;
    const float* nrm = DENSE ? d_dis    : d_dinv;

    constexpr int V = D / 32;  // 1, 2 or 4
    int gw = (blockIdx.x * blockDim.x + threadIdx.x) >> 5;
    int lane = threadIdx.x & 31;
    if (gw >= NN) return;

    float acc[V];
#pragma unroll
    for (int v = 0; v < V; v++) acc[v] = 0.f;

    int beg = rp[gw], end = rp[gw + 1];
    int p = beg;
    constexpr int U = 8;
    for (; p + U <= end; p += U) {
        int j[U]; float n[U];
#pragma unroll
        for (int u = 0; u < U; u++) j[u] = nb[p + u];
#pragma unroll
        for (int u = 0; u < U; u++) n[u] = nrm[j[u]];
        if (V == 4) {
            float4 x[U];
#pragma unroll
            for (int u = 0; u < U; u++) x[u] = *(const float4*)&X[j[u] * D + lane * 4];
#pragma unroll
            for (int u = 0; u < U; u++) {
                acc[0] += n[u] * x[u].x; acc[1] += n[u] * x[u].y;
                acc[2] += n[u] * x[u].z; acc[3] += n[u] * x[u].w;
            }
        } else if (V == 2) {
            float2 x[U];
#pragma unroll
            for (int u = 0; u < U; u++) x[u] = *(const float2*)&X[j[u] * D + lane * 2];
#pragma unroll
            for (int u = 0; u < U; u++) { acc[0] += n[u] * x[u].x; acc[1] += n[u] * x[u].y; }
        } else {
            float x[U];
#pragma unroll
            for (int u = 0; u < U; u++) x[u] = X[j[u] * D + lane];
#pragma unroll
            for (int u = 0; u < U; u++) acc[0] += n[u] * x[u];
        }
    }
    for (; p < end; p++) {
        int j = nb[p];
        float nj = nrm[j];
        if (V == 4) {
            float4 x = *(const float4*)&X[j * D + lane * 4];
            acc[0] += nj * x.x; acc[1] += nj * x.y; acc[2] += nj * x.z; acc[3] += nj * x.w;
        } else if (V == 2) {
            float2 x = *(const float2*)&X[j * D + lane * 2];
            acc[0] += nj * x.x; acc[1] += nj * x.y;
        } else {
            acc[0] += nj * X[j * D + lane];
        }
    }
    float ni = nrm[gw], ni2 = ni * ni;
#pragma unroll
    for (int v = 0; v < V; v++) {
        float r = ni * acc[v] + ni2 * X[gw * D + lane * V + v];
        if (BIASRELU) r = fmaxf(r + bias[lane * V + v], 0.f);
        Y[gw * D + lane * V + v] = r;
    }
}

// ---------------- L5 GEMM: warp per row, bufA[N,128] @ W[128,6] -> d_g ----------------
__global__ void k_gemm6(const float* __restrict__ W) {
    const float* X = d_bufA;
    int row = (blockIdx.x * blockDim.x + threadIdx.x) >> 5;
    int lane = threadIdx.x & 31;
    if (row >= NN) return;
    float acc[6] = {0.f, 0.f, 0.f, 0.f, 0.f, 0.f};
#pragma unroll
    for (int kb = 0; kb < 4; kb++) {
        int k = kb * 32 + lane;
        float x = X[row * 128 + k];
#pragma unroll
        for (int c = 0; c < 6; c++) acc[c] += x * W[k * 6 + c];
    }
#pragma unroll
    for (int c = 0; c < 6; c++) {
#pragma unroll
        for (int off = 16; off >= 1; off >>= 1)
            acc[c] += __shfl_xor_sync(0xFFFFFFFF, acc[c], off);
    }
    if (lane == 0) {
#pragma unroll
        for (int c = 0; c < 6; c++) d_g[row * 8 + c] = acc[c];
    }
}

// ---------------- final: sparse agg over 6 channels + bias + log_softmax ----------------
__global__ void k_final(const float* __restrict__ b2, float* __restrict__ out) {
    int i = blockIdx.x * blockDim.x + threadIdx.x;
    if (i >= NN) return;
    float a0 = 0, a1 = 0, a2 = 0, a3 = 0, a4 = 0, a5 = 0;
    int beg = d_rp_dst[i], end = d_rp_dst[i + 1];
    int p = beg;
    for (; p + 2 <= end; p += 2) {
        int j0 = d_nb_dst[p], j1 = d_nb_dst[p + 1];
        float n0 = d_dinv[j0], n1 = d_dinv[j1];
        float4 u0 = *(const float4*)&d_g[j0 * 8];
        float2 v0 = *(const float2*)&d_g[j0 * 8 + 4];
        float4 u1 = *(const float4*)&d_g[j1 * 8];
        float2 v1 = *(const float2*)&d_g[j1 * 8 + 4];
        a0 += n0 * u0.x + n1 * u1.x;  a1 += n0 * u0.y + n1 * u1.y;
        a2 += n0 * u0.z + n1 * u1.z;  a3 += n0 * u0.w + n1 * u1.w;
        a4 += n0 * v0.x + n1 * v1.x;  a5 += n0 * v0.y + n1 * v1.y;
    }
    for (; p < end; p++) {
        int j = d_nb_dst[p];
        float nj = d_dinv[j];
        float4 u = *(const float4*)&d_g[j * 8];
        float2 v = *(const float2*)&d_g[j * 8 + 4];
        a0 += nj * u.x; a1 += nj * u.y; a2 += nj * u.z;
        a3 += nj * u.w; a4 += nj * v.x; a5 += nj * v.y;
    }
    float ni = d_dinv[i], ni2 = ni * ni;
    float4 su = *(const float4*)&d_g[i * 8];
    float2 sv = *(const float2*)&d_g[i * 8 + 4];
    float r[6];
    r[0] = ni * a0 + ni2 * su.x + b2[0];
    r[1] = ni * a1 + ni2 * su.y + b2[1];
    r[2] = ni * a2 + ni2 * su.z + b2[2];
    r[3] = ni * a3 + ni2 * su.w + b2[3];
    r[4] = ni * a4 + ni2 * sv.x + b2[4];
    r[5] = ni * a5 + ni2 * sv.y + b2[5];
    float m = r[0];
#pragma unroll
    for (int c = 1; c < 6; c++) m = fmaxf(m, r[c]);
    float s = 0.f;
#pragma unroll
    for (int c = 0; c < 6; c++) s += expf(r[c] - m);
    float l = logf(s);
#pragma unroll
    for (int c = 0; c < 6; c++) out[i * 6 + c] = r[c] - m - l;
}

// ---------------- launch ----------------
static int idx_of(const int* in_sizes, int n_in, int size, int ordinal) {
    int c = 0;
    for (int i = 0; i < n_in; i++) {
        if (in_sizes[i] == size) {
            if (c == ordinal) return i;
            c++;
        }
    }
    return 0;
}

extern "C" void kernel_launch(void* const* d_in, const int* in_sizes, int n_in,
                              void* d_out, int out_size) {
    const float* feats = (const float*)d_in[idx_of(in_sizes, n_in, NN * 512, 0)];
    const int*   e32   = (const int*)d_in[idx_of(in_sizes, n_in, 2 * EE, 0)];
    const float* W1  = (const float*)d_in[idx_of(in_sizes, n_in, 512 * 32, 0)];
    const float* b1  = (const float*)d_in[idx_of(in_sizes, n_in, 32, 0)];
    const float* W12 = (const float*)d_in[idx_of(in_sizes, n_in, 32 * 64, 0)];
    const float* b12 = (const float*)d_in[idx_of(in_sizes, n_in, 64, 0)];
    const float* W13 = (const float*)d_in[idx_of(in_sizes, n_in, 64 * 128, 0)];
    const float* b13 = (const float*)d_in[idx_of(in_sizes, n_in, 128, 0)];
    const float* W14 = (const float*)d_in[idx_of(in_sizes, n_in, 128 * 128, 1)];  // 2nd 16384
    const float* b14 = (const float*)d_in[idx_of(in_sizes, n_in, 128, 1)];        // 2nd 128
    const float* W2  = (const float*)d_in[idx_of(in_sizes, n_in, 128 * 6, 0)];
    const float* b2  = (const float*)d_in[idx_of(in_sizes, n_in, 6, 0)];
    float* out = (float*)d_out;

    // Side stream + fork/join events. Host-side objects only (no device memory);
    // created once on the first (non-capturing correctness) call. The captured
    // GPU work is identical on every invocation.
    static cudaStream_t s1 = nullptr;
    static cudaEvent_t evFork = nullptr, evJoin = nullptr;
    if (s1 == nullptr) {
        cudaStreamCreateWithFlags(&s1, cudaStreamNonBlocking);
        cudaEventCreateWithFlags(&evFork, cudaEventDisableTiming);
        cudaEventCreateWithFlags(&evJoin, cudaEventDisableTiming);
    }

    // Fork: L1 GEMM chain (feats/W1 -> d_split -> bufB) runs on s1, concurrent
    // with the CSR build chain (edges -> rp/nb/nrm) on the main stream. The two
    // chains touch disjoint memory and first meet at the dense aggregation.
    cudaEventRecord(evFork, 0);
    cudaStreamWaitEvent(s1, evFork, 0);

    // s1: L1 split-K(8) GEMM feats@W1 -> d_split[NN][8x32]; reduce to bufB[NN][32]
    k_gemm<512, 32, 128, 32, 4, 8, false, false, 0, 3>
        <<<dim3(cdiv(NN, 128), 8), dim3(8, 32), 0, s1>>>(feats, W1, nullptr);
    k_reduce8<<<cdiv(NN * 8, 256), 256, 0, s1>>>();
    cudaEventRecord(evJoin, s1);

    // main stream: CSR build (cnt arrays zero: static init + re-zero in k_scan)
    k_count<<<cdiv(EE, 256), 256>>>(e32);
    k_scan<<<1, 1024>>>();
    k_place<<<cdiv(EE, 256), 256>>>(e32);

    // Join: dense agg needs both bufB (s1) and CSR (main)
    cudaStreamWaitEvent(0, evJoin, 0);

    // L1 dense agg (B->A) + b1 + relu
    k_agg<32, true, 2, true><<<cdiv(NN * 32, 256), 256>>>(b1);

    // L2: dense agg at 32 (A->B), then GEMM 32->64 (B->A) + b12 + relu
    k_agg<32, false, 1, true><<<cdiv(NN * 32, 256), 256>>>(nullptr);
    k_gemm<32, 64, 64, 16, 4, 1, true, true, 2, 1><<<cdiv(NN, 64), dim3(16, 16)>>>(nullptr, W12, b12);

    // L3: sparse agg at 64 (A->B), then GEMM 64->128 (B->A) + b13 + relu
    k_agg<64, false, 1, false><<<cdiv(NN * 32, 256), 256>>>(nullptr);
    k_gemm<64, 128, 64, 16, 8, 1, true, true, 2, 1><<<cdiv(NN, 64), dim3(32, 8)>>>(nullptr, W13, b13);

    // L4: sparse agg at 128 (A->B), then GEMM 128->128 (B->A) + b14 + relu
    k_agg<128, false, 1, false><<<cdiv(NN * 32, 256), 256>>>(nullptr);
    k_gemm<128, 128, 64, 16, 8, 1, true, true, 2, 1><<<cdiv(NN, 64), dim3(32, 8)>>>(nullptr, W14, b14);

    // L5: GEMM 128->6 first (A -> d_g), then sparse agg at 6 + b2 + log_softmax
    k_gemm6<<<cdiv(NN * 32, 256), 256>>>(W2);
    k_final<<<cdiv(NN, 256), 256>>>(b2, out);
}